// round 1
// baseline (speedup 1.0000x reference)
#include <cuda_runtime.h>
#include <cuda_bf16.h>
#include <math.h>

// Problem constants
#define BATCH 4
#define TLEN 2048
#define DMODEL 2048
#define DHALF 1024
#define NROWS (BATCH * TLEN)          // 8192
#define KGIST 16
#define NHEADS 16
#define HDIM 128
#define KPAD 1040                      // 1025 padded to mult of 16 (and of 4)

// ------------------------- scratch (device globals; no allocation) ---------
__device__ float g_y [NROWS * DMODEL];
__device__ float g_u [NROWS * DMODEL];
__device__ float g_x1[NROWS * DMODEL];
__device__ float g_x2[NROWS * DMODEL];
__device__ float g_q [NROWS * DMODEL];
__device__ float g_feat[BATCH * KGIST * KPAD];
__device__ float g_upw [DMODEL * KPAD];
__device__ float g_repr[BATCH * KGIST * DMODEL];
__device__ float g_kh  [BATCH * KGIST * DMODEL];
__device__ float g_v   [BATCH * KGIST * DMODEL];
__device__ float g_shc[4 * DHALF];
__device__ float g_shs[4 * DHALF];
__device__ float g_gc [BATCH * DHALF];
__device__ float g_gs [BATCH * DHALF];

// ------------------------- helpers -----------------------------------------
__device__ __forceinline__ float block_reduce_sum256(float v) {
    __shared__ float sb[8];
    int lane = threadIdx.x & 31, wid = threadIdx.x >> 5;
    #pragma unroll
    for (int o = 16; o > 0; o >>= 1) v += __shfl_xor_sync(0xffffffffu, v, o);
    if (lane == 0) sb[wid] = v;
    __syncthreads();
    float r = 0.f;
    #pragma unroll
    for (int i = 0; i < 8; i++) r += sb[i];
    __syncthreads();
    return r;
}

// ------------------------- small prep kernels -------------------------------
__global__ void prep_sheaf_cs_kernel(const float* __restrict__ thetas,
                                     float* __restrict__ c, float* __restrict__ s) {
    int i = blockIdx.x * 256 + threadIdx.x;
    if (i < 4 * DHALF) { float th = thetas[i]; c[i] = cosf(th); s[i] = sinf(th); }
}

__global__ void gist_theta_kernel(const float* __restrict__ gtheta,
                                  const float* __restrict__ gmag,
                                  const float* __restrict__ gw,
                                  const float* __restrict__ gstrength,
                                  float* __restrict__ gc, float* __restrict__ gs) {
    int b = blockIdx.x;
    float wk[KGIST]; float wsum = 0.f;
    #pragma unroll
    for (int k = 0; k < KGIST; k++) { wk[k] = gw[b * KGIST + k] * gmag[b * KGIST + k]; wsum += wk[k]; }
    float inv = 1.f / (wsum + 1e-8f);
    float sig = 1.f / (1.f + expf(-gstrength[0]));
    for (int p = threadIdx.x; p < DHALF; p += 256) {
        float th = 0.f;
        #pragma unroll
        for (int k = 0; k < KGIST; k++) th += (wk[k] * inv) * gtheta[(size_t)(b * KGIST + k) * DHALF + p];
        th *= sig;
        gc[b * DHALF + p] = cosf(th);
        gs[b * DHALF + p] = sinf(th);
    }
}

__global__ void feat_kernel(const float* __restrict__ gtheta,
                            const float* __restrict__ gmag,
                            float* __restrict__ feat) {
    int r = blockIdx.x;           // b*16+k, 0..63
    for (int f = threadIdx.x; f < KPAD; f += 256) {
        float v = 0.f;
        if (f < DHALF) v = gtheta[(size_t)r * DHALF + f];
        else if (f == DHALF) v = gmag[r];
        feat[(size_t)r * KPAD + f] = v;
    }
}

__global__ void pad_upw_kernel(const float* __restrict__ upw, float* __restrict__ dst) {
    int o = blockIdx.x;           // 0..2047
    for (int f = threadIdx.x; f < KPAD; f += 256) {
        float v = (f < (DHALF + 1)) ? upw[(size_t)o * (DHALF + 1) + f] : 0.f;
        dst[(size_t)o * KPAD + f] = v;
    }
}

// ------------------------- LayerNorm ----------------------------------------
__global__ void ln_kernel(const float* __restrict__ in,
                          const float* __restrict__ w,
                          const float* __restrict__ b,
                          float* __restrict__ out) {
    int row = blockIdx.x;
    const float* p = in + (size_t)row * DMODEL;
    float v[8];
    #pragma unroll
    for (int j = 0; j < 8; j++) v[j] = p[threadIdx.x + 256 * j];
    float s = 0.f;
    #pragma unroll
    for (int j = 0; j < 8; j++) s += v[j];
    float mean = block_reduce_sum256(s) * (1.f / DMODEL);
    float q = 0.f;
    #pragma unroll
    for (int j = 0; j < 8; j++) { float d = v[j] - mean; q += d * d; }
    float var = block_reduce_sum256(q) * (1.f / DMODEL);
    float rstd = rsqrtf(var + 1e-5f);
    #pragma unroll
    for (int j = 0; j < 8; j++) {
        int i = threadIdx.x + 256 * j;
        out[(size_t)row * DMODEL + i] = (v[j] - mean) * rstd * w[i] + b[i];
    }
}

// ------------------------- sheaf (rotations + temporal laplacian) -----------
__global__ void sheaf_kernel(const float* __restrict__ y,
                             const float* __restrict__ ctab,
                             const float* __restrict__ stab,
                             const float* __restrict__ alpha_p,
                             float* __restrict__ u) {
    int row = blockIdx.x;
    int t = row & (TLEN - 1);
    float a = fabsf(alpha_p[0]);
    const float* yr = y + (size_t)row * DMODEL;
    #pragma unroll
    for (int jj = 0; jj < 4; jj++) {
        int p = threadIdx.x + 256 * jj;     // 0..1023
        float r0 = yr[p], i0 = yr[p + DHALF];
        float lr = 4.f * r0, li = 4.f * i0;
        #pragma unroll
        for (int idx = 0; idx < 4; idx++) {
            int delta = idx - 3;            // offsets -3,-2,-1,0
            float rs, is;
            if (delta == 0) { rs = r0; is = i0; }
            else if (t + delta >= 0) {
                const float* ys = y + (size_t)(row + delta) * DMODEL;
                rs = ys[p]; is = ys[p + DHALF];
            } else { rs = 0.f; is = 0.f; }
            float c = ctab[idx * DHALF + p], s = stab[idx * DHALF + p];
            lr -= c * rs + s * is;
            li -= c * is - s * rs;
        }
        u[(size_t)row * DMODEL + p]         = r0 - a * lr;
        u[(size_t)row * DMODEL + p + DHALF] = i0 - a * li;
    }
}

// ------------------------- fused gist rotation block ------------------------
// x2 = x1 + LN_gr(rot_fwd(LN_gist(x1), c_b, s_b)) - LN_gist(x1)
__global__ void gist_rot_kernel(const float* __restrict__ x1,
                                const float* __restrict__ lw, const float* __restrict__ lb,
                                const float* __restrict__ grw, const float* __restrict__ grb,
                                const float* __restrict__ gc, const float* __restrict__ gs,
                                float* __restrict__ x2) {
    int row = blockIdx.x;
    int b = row >> 11;
    const float* p = x1 + (size_t)row * DMODEL;
    float xr[4], xi[4];
    #pragma unroll
    for (int jj = 0; jj < 4; jj++) {
        int q = threadIdx.x + 256 * jj;
        xr[jj] = p[q]; xi[jj] = p[q + DHALF];
    }
    float s1 = 0.f;
    #pragma unroll
    for (int jj = 0; jj < 4; jj++) s1 += xr[jj] + xi[jj];
    float m1 = block_reduce_sum256(s1) * (1.f / DMODEL);
    float q1 = 0.f;
    #pragma unroll
    for (int jj = 0; jj < 4; jj++) {
        float dr = xr[jj] - m1, di = xi[jj] - m1;
        q1 += dr * dr + di * di;
    }
    float rstd1 = rsqrtf(block_reduce_sum256(q1) * (1.f / DMODEL) + 1e-5f);

    float xnr[4], xni[4], rr[4], ri[4];
    #pragma unroll
    for (int jj = 0; jj < 4; jj++) {
        int q = threadIdx.x + 256 * jj;
        xnr[jj] = (xr[jj] - m1) * rstd1 * lw[q] + lb[q];
        xni[jj] = (xi[jj] - m1) * rstd1 * lw[q + DHALF] + lb[q + DHALF];
        float c = gc[b * DHALF + q], sn = gs[b * DHALF + q];
        rr[jj] = xnr[jj] * c - xni[jj] * sn;
        ri[jj] = xnr[jj] * sn + xni[jj] * c;
    }
    float s2 = 0.f;
    #pragma unroll
    for (int jj = 0; jj < 4; jj++) s2 += rr[jj] + ri[jj];
    float m2 = block_reduce_sum256(s2) * (1.f / DMODEL);
    float q2 = 0.f;
    #pragma unroll
    for (int jj = 0; jj < 4; jj++) {
        float dr = rr[jj] - m2, di = ri[jj] - m2;
        q2 += dr * dr + di * di;
    }
    float rstd2 = rsqrtf(block_reduce_sum256(q2) * (1.f / DMODEL) + 1e-5f);

    #pragma unroll
    for (int jj = 0; jj < 4; jj++) {
        int q = threadIdx.x + 256 * jj;
        float outr = xr[jj] + (rr[jj] - m2) * rstd2 * grw[q] + grb[q] - xnr[jj];
        float outi = xi[jj] + (ri[jj] - m2) * rstd2 * grw[q + DHALF] + grb[q + DHALF] - xni[jj];
        x2[(size_t)row * DMODEL + q]         = outr;
        x2[(size_t)row * DMODEL + q + DHALF] = outi;
    }
}

// ------------------------- tiled fp32 GEMM: C[m,n] = sum_k A[m,k]*W[n,k] ----
// D = C + bias[n]? + add1[m,n]? + add2[m,n]?     (N fixed at 2048)
__global__ __launch_bounds__(256, 2)
void gemm_kernel(const float* __restrict__ A, int lda,
                 const float* __restrict__ W, int ldb,
                 float* __restrict__ D, int ldd,
                 const float* __restrict__ add1,
                 const float* __restrict__ add2,
                 const float* __restrict__ bias,
                 int M, int Kdim) {
    __shared__ float As[16][132];
    __shared__ float Bs[16][132];
    const int m0 = blockIdx.y * 128, n0 = blockIdx.x * 128;
    const int tid = threadIdx.x, tx = tid & 15, ty = tid >> 4;
    float acc[8][8];
    #pragma unroll
    for (int i = 0; i < 8; i++)
        #pragma unroll
        for (int j = 0; j < 8; j++) acc[i][j] = 0.f;

    for (int k0 = 0; k0 < Kdim; k0 += 16) {
        #pragma unroll
        for (int i = 0; i < 2; i++) {
            int f  = tid + 256 * i;      // 0..511
            int rm = f >> 2;             // 0..127
            int kc = (f & 3) << 2;       // 0,4,8,12
            float4 av = make_float4(0.f, 0.f, 0.f, 0.f);
            if (m0 + rm < M) av = *(const float4*)(A + (size_t)(m0 + rm) * lda + k0 + kc);
            As[kc + 0][rm] = av.x; As[kc + 1][rm] = av.y;
            As[kc + 2][rm] = av.z; As[kc + 3][rm] = av.w;
            float4 bv = *(const float4*)(W + (size_t)(n0 + rm) * ldb + k0 + kc);
            Bs[kc + 0][rm] = bv.x; Bs[kc + 1][rm] = bv.y;
            Bs[kc + 2][rm] = bv.z; Bs[kc + 3][rm] = bv.w;
        }
        __syncthreads();
        #pragma unroll
        for (int k = 0; k < 16; k++) {
            float ra[8], rb[8];
            #pragma unroll
            for (int i = 0; i < 8; i++) ra[i] = As[k][ty * 8 + i];
            #pragma unroll
            for (int j = 0; j < 8; j++) rb[j] = Bs[k][tx * 8 + j];
            #pragma unroll
            for (int i = 0; i < 8; i++)
                #pragma unroll
                for (int j = 0; j < 8; j++) acc[i][j] += ra[i] * rb[j];
        }
        __syncthreads();
    }

    #pragma unroll
    for (int i = 0; i < 8; i++) {
        int m = m0 + ty * 8 + i;
        if (m < M) {
            #pragma unroll
            for (int j = 0; j < 8; j++) {
                int n = n0 + tx * 8 + j;
                float v = acc[i][j];
                if (bias) v += bias[n];
                size_t idx = (size_t)m * ldd + n;
                if (add1) v += add1[idx];
                if (add2) v += add2[idx];
                D[idx] = v;
            }
        }
    }
}

// ------------------------- gist cross-attention (16 kv tokens) ---------------
__global__ void attn_kernel(const float* __restrict__ Q,
                            const float* __restrict__ Kh,
                            const float* __restrict__ V,
                            float* __restrict__ ctx) {
    __shared__ float Ks[KGIST][HDIM];
    __shared__ float Vs[KGIST][HDIM];
    const int h = blockIdx.y, b = blockIdx.z;
    const int t0 = blockIdx.x * 32;
    for (int j = threadIdx.x; j < KGIST * HDIM; j += 256) {
        int k = j >> 7, c = j & 127;
        Ks[k][c] = Kh[(size_t)(b * KGIST + k) * DMODEL + h * HDIM + c];
        Vs[k][c] = V [(size_t)(b * KGIST + k) * DMODEL + h * HDIM + c];
    }
    __syncthreads();
    const int w = threadIdx.x >> 5, lane = threadIdx.x & 31;
    const float scale = 0.08838834764831845f;   // 1/sqrt(128)
    for (int it = 0; it < 4; it++) {
        int t = t0 + w * 4 + it;
        size_t base = ((size_t)(b * TLEN + t)) * DMODEL + h * HDIM + lane * 4;
        float q0 = Q[base], q1 = Q[base + 1], q2 = Q[base + 2], q3 = Q[base + 3];
        float sc[KGIST];
        #pragma unroll
        for (int k = 0; k < KGIST; k++) {
            float ps = q0 * Ks[k][lane * 4] + q1 * Ks[k][lane * 4 + 1]
                     + q2 * Ks[k][lane * 4 + 2] + q3 * Ks[k][lane * 4 + 3];
            #pragma unroll
            for (int o = 16; o > 0; o >>= 1) ps += __shfl_xor_sync(0xffffffffu, ps, o);
            sc[k] = ps * scale;
        }
        float mx = sc[0];
        #pragma unroll
        for (int k = 1; k < KGIST; k++) mx = fmaxf(mx, sc[k]);
        float ssum = 0.f;
        #pragma unroll
        for (int k = 0; k < KGIST; k++) { sc[k] = expf(sc[k] - mx); ssum += sc[k]; }
        float inv = 1.f / ssum;
        float c0 = 0.f, c1 = 0.f, c2 = 0.f, c3 = 0.f;
        #pragma unroll
        for (int k = 0; k < KGIST; k++) {
            float wk = sc[k] * inv;
            c0 += wk * Vs[k][lane * 4];
            c1 += wk * Vs[k][lane * 4 + 1];
            c2 += wk * Vs[k][lane * 4 + 2];
            c3 += wk * Vs[k][lane * 4 + 3];
        }
        ctx[base] = c0; ctx[base + 1] = c1; ctx[base + 2] = c2; ctx[base + 3] = c3;
    }
}

// ------------------------- launcher -----------------------------------------
extern "C" void kernel_launch(void* const* d_in, const int* in_sizes, int n_in,
                              void* d_out, int out_size) {
    const float* x             = (const float*)d_in[0];
    const float* gist_theta    = (const float*)d_in[1];
    const float* gist_mag      = (const float*)d_in[2];
    const float* gist_weights  = (const float*)d_in[3];
    const float* ln_sheaf_w    = (const float*)d_in[4];
    const float* ln_sheaf_b    = (const float*)d_in[5];
    const float* sheaf_thetas  = (const float*)d_in[6];
    const float* alpha         = (const float*)d_in[7];
    const float* corr_W        = (const float*)d_in[8];
    const float* ln_gist_w     = (const float*)d_in[9];
    const float* ln_gist_b     = (const float*)d_in[10];
    const float* gist_strength = (const float*)d_in[11];
    const float* gr_ln_w       = (const float*)d_in[12];
    const float* gr_ln_b       = (const float*)d_in[13];
    const float* ln_gca_w      = (const float*)d_in[14];
    const float* ln_gca_b      = (const float*)d_in[15];
    const float* Wq            = (const float*)d_in[16];
    const float* Wk            = (const float*)d_in[17];
    const float* Wv            = (const float*)d_in[18];
    const float* Wo            = (const float*)d_in[19];
    const float* gist_up_W     = (const float*)d_in[20];
    const float* gist_up_b     = (const float*)d_in[21];
    float* out = (float*)d_out;

    float *y, *u, *x1, *x2, *q, *feat, *upw, *repr, *kh, *v, *shc, *shs, *gc, *gs;
    cudaGetSymbolAddress((void**)&y,    g_y);
    cudaGetSymbolAddress((void**)&u,    g_u);
    cudaGetSymbolAddress((void**)&x1,   g_x1);
    cudaGetSymbolAddress((void**)&x2,   g_x2);
    cudaGetSymbolAddress((void**)&q,    g_q);
    cudaGetSymbolAddress((void**)&feat, g_feat);
    cudaGetSymbolAddress((void**)&upw,  g_upw);
    cudaGetSymbolAddress((void**)&repr, g_repr);
    cudaGetSymbolAddress((void**)&kh,   g_kh);
    cudaGetSymbolAddress((void**)&v,    g_v);
    cudaGetSymbolAddress((void**)&shc,  g_shc);
    cudaGetSymbolAddress((void**)&shs,  g_shs);
    cudaGetSymbolAddress((void**)&gc,   g_gc);
    cudaGetSymbolAddress((void**)&gs,   g_gs);

    dim3 gbig(16, NROWS / 128);   // big GEMMs
    dim3 gsm(16, 1);              // M=64 GEMMs

    // prep
    prep_sheaf_cs_kernel<<<16, 256>>>(sheaf_thetas, shc, shs);
    gist_theta_kernel<<<BATCH, 256>>>(gist_theta, gist_mag, gist_weights, gist_strength, gc, gs);
    feat_kernel<<<BATCH * KGIST, 256>>>(gist_theta, gist_mag, feat);
    pad_upw_kernel<<<DMODEL, 256>>>(gist_up_W, upw);

    // stage 1: sheaf residual
    ln_kernel<<<NROWS, 256>>>(x, ln_sheaf_w, ln_sheaf_b, y);
    sheaf_kernel<<<NROWS, 256>>>(y, shc, shs, alpha, u);
    gemm_kernel<<<gbig, 256>>>(u, DMODEL, corr_W, DMODEL, x1, DMODEL, x, u, nullptr, NROWS, DMODEL);

    // gist K/V path (tiny)
    gemm_kernel<<<gsm, 256>>>(feat, KPAD, upw, KPAD, repr, DMODEL, nullptr, nullptr, gist_up_b, BATCH * KGIST, KPAD);
    gemm_kernel<<<gsm, 256>>>(repr, DMODEL, Wk, DMODEL, kh, DMODEL, nullptr, nullptr, nullptr, BATCH * KGIST, DMODEL);
    gemm_kernel<<<gsm, 256>>>(repr, DMODEL, Wv, DMODEL, v,  DMODEL, nullptr, nullptr, nullptr, BATCH * KGIST, DMODEL);

    // stage 2: gist rotation residual (fused)
    gist_rot_kernel<<<NROWS, 256>>>(x1, ln_gist_w, ln_gist_b, gr_ln_w, gr_ln_b, gc, gs, x2);

    // stage 3: gist cross-attention residual
    ln_kernel<<<NROWS, 256>>>(x2, ln_gca_w, ln_gca_b, y);
    gemm_kernel<<<gbig, 256>>>(y, DMODEL, Wq, DMODEL, q, DMODEL, nullptr, nullptr, nullptr, NROWS, DMODEL);
    attn_kernel<<<dim3(TLEN / 32, NHEADS, BATCH), 256>>>(q, kh, v, u);
    gemm_kernel<<<gbig, 256>>>(u, DMODEL, Wo, DMODEL, out, DMODEL, x2, nullptr, nullptr, NROWS, DMODEL);

    (void)in_sizes; (void)n_in; (void)out_size;
}

// round 3
// speedup vs baseline: 2.0952x; 2.0952x over previous
#include <cuda_runtime.h>
#include <cuda_bf16.h>
#include <cuda.h>
#include <math.h>
#include <cstdint>

// Problem constants
#define BATCH 4
#define TLEN 2048
#define DMODEL 2048
#define DHALF 1024
#define NROWS (BATCH * TLEN)          // 8192
#define KGIST 16
#define NHEADS 16
#define HDIM 128
#define KPAD 1040

// ------------------------- scratch (device globals; no allocation) ---------
__device__ float g_y [NROWS * DMODEL];
__device__ float g_u [NROWS * DMODEL];
__device__ float g_x1[NROWS * DMODEL];
__device__ float g_x2[NROWS * DMODEL];
__device__ float g_q [NROWS * DMODEL];
__device__ __nv_bfloat16 g_ahi[NROWS * DMODEL];
__device__ __nv_bfloat16 g_alo[NROWS * DMODEL];
__device__ __nv_bfloat16 g_whi[DMODEL * DMODEL];
__device__ __nv_bfloat16 g_wlo[DMODEL * DMODEL];
__device__ float g_feat[BATCH * KGIST * KPAD];
__device__ float g_upw [DMODEL * KPAD];
__device__ float g_repr[BATCH * KGIST * DMODEL];
__device__ float g_kh  [BATCH * KGIST * DMODEL];
__device__ float g_v   [BATCH * KGIST * DMODEL];
__device__ float g_shc[4 * DHALF];
__device__ float g_shs[4 * DHALF];
__device__ float g_gc [BATCH * DHALF];
__device__ float g_gs [BATCH * DHALF];

// ------------------------- helpers -----------------------------------------
__device__ __forceinline__ uint32_t smem_u32(const void* p) {
    uint32_t a;
    asm("{ .reg .u64 t; cvta.to.shared.u64 t, %1; cvt.u32.u64 %0, t; }" : "=r"(a) : "l"(p));
    return a;
}

__device__ __forceinline__ void cpasync16(uint32_t dst, const void* src) {
    asm volatile("cp.async.cg.shared.global [%0], [%1], 16;" :: "r"(dst), "l"(src));
}
#define CP_COMMIT() asm volatile("cp.async.commit_group;" ::: "memory")
#define CP_WAIT(n)  asm volatile("cp.async.wait_group %0;" :: "n"(n) : "memory")

__device__ __forceinline__ float block_reduce_sum256(float v) {
    __shared__ float sb[8];
    int lane = threadIdx.x & 31, wid = threadIdx.x >> 5;
    #pragma unroll
    for (int o = 16; o > 0; o >>= 1) v += __shfl_xor_sync(0xffffffffu, v, o);
    if (lane == 0) sb[wid] = v;
    __syncthreads();
    float r = 0.f;
    #pragma unroll
    for (int i = 0; i < 8; i++) r += sb[i];
    __syncthreads();
    return r;
}

__device__ __forceinline__ void split_hi_lo(float v, __nv_bfloat16& h, __nv_bfloat16& l) {
    h = __float2bfloat16(v);
    l = __float2bfloat16(v - __bfloat162float(h));
}

__device__ __forceinline__ void mma16816(float* d, const uint32_t* a, uint32_t b0, uint32_t b1) {
    asm volatile(
        "mma.sync.aligned.m16n8k16.row.col.f32.bf16.bf16.f32 "
        "{%0,%1,%2,%3}, {%4,%5,%6,%7}, {%8,%9}, {%0,%1,%2,%3};"
        : "+f"(d[0]), "+f"(d[1]), "+f"(d[2]), "+f"(d[3])
        : "r"(a[0]), "r"(a[1]), "r"(a[2]), "r"(a[3]), "r"(b0), "r"(b1));
}

// ------------------------- small prep kernels -------------------------------
__global__ void prep_sheaf_cs_kernel(const float* __restrict__ thetas,
                                     float* __restrict__ c, float* __restrict__ s) {
    int i = blockIdx.x * 256 + threadIdx.x;
    if (i < 4 * DHALF) { float th = thetas[i]; c[i] = cosf(th); s[i] = sinf(th); }
}

__global__ void gist_theta_kernel(const float* __restrict__ gtheta,
                                  const float* __restrict__ gmag,
                                  const float* __restrict__ gw,
                                  const float* __restrict__ gstrength,
                                  float* __restrict__ gc, float* __restrict__ gs) {
    int b = blockIdx.x;
    float wk[KGIST]; float wsum = 0.f;
    #pragma unroll
    for (int k = 0; k < KGIST; k++) { wk[k] = gw[b * KGIST + k] * gmag[b * KGIST + k]; wsum += wk[k]; }
    float inv = 1.f / (wsum + 1e-8f);
    float sig = 1.f / (1.f + expf(-gstrength[0]));
    for (int p = threadIdx.x; p < DHALF; p += 256) {
        float th = 0.f;
        #pragma unroll
        for (int k = 0; k < KGIST; k++) th += (wk[k] * inv) * gtheta[(size_t)(b * KGIST + k) * DHALF + p];
        th *= sig;
        gc[b * DHALF + p] = cosf(th);
        gs[b * DHALF + p] = sinf(th);
    }
}

__global__ void feat_kernel(const float* __restrict__ gtheta,
                            const float* __restrict__ gmag,
                            float* __restrict__ feat) {
    int r = blockIdx.x;
    for (int f = threadIdx.x; f < KPAD; f += 256) {
        float v = 0.f;
        if (f < DHALF) v = gtheta[(size_t)r * DHALF + f];
        else if (f == DHALF) v = gmag[r];
        feat[(size_t)r * KPAD + f] = v;
    }
}

__global__ void pad_upw_kernel(const float* __restrict__ upw, float* __restrict__ dst) {
    int o = blockIdx.x;
    for (int f = threadIdx.x; f < KPAD; f += 256) {
        float v = (f < (DHALF + 1)) ? upw[(size_t)o * (DHALF + 1) + f] : 0.f;
        dst[(size_t)o * KPAD + f] = v;
    }
}

// fp32 -> bf16 hi/lo splitter (weights)
__global__ void split_kernel(const float* __restrict__ in,
                             __nv_bfloat16* __restrict__ hi,
                             __nv_bfloat16* __restrict__ lo, int n4) {
    int i = blockIdx.x * 256 + threadIdx.x;
    if (i >= n4) return;
    float4 v = ((const float4*)in)[i];
    __nv_bfloat16 h0, h1, h2, h3, l0, l1, l2, l3;
    split_hi_lo(v.x, h0, l0); split_hi_lo(v.y, h1, l1);
    split_hi_lo(v.z, h2, l2); split_hi_lo(v.w, h3, l3);
    ((__nv_bfloat162*)hi)[2 * i]     = __nv_bfloat162(h0, h1);
    ((__nv_bfloat162*)hi)[2 * i + 1] = __nv_bfloat162(h2, h3);
    ((__nv_bfloat162*)lo)[2 * i]     = __nv_bfloat162(l0, l1);
    ((__nv_bfloat162*)lo)[2 * i + 1] = __nv_bfloat162(l2, l3);
}

// ------------------------- LayerNorm (optionally emits bf16 hi/lo) ---------
__global__ void ln_kernel(const float* __restrict__ in,
                          const float* __restrict__ w,
                          const float* __restrict__ b,
                          float* __restrict__ outf,
                          __nv_bfloat16* __restrict__ outh,
                          __nv_bfloat16* __restrict__ outl) {
    int row = blockIdx.x;
    const float* p = in + (size_t)row * DMODEL;
    float v[8];
    #pragma unroll
    for (int j = 0; j < 8; j++) v[j] = p[threadIdx.x + 256 * j];
    float s = 0.f;
    #pragma unroll
    for (int j = 0; j < 8; j++) s += v[j];
    float mean = block_reduce_sum256(s) * (1.f / DMODEL);
    float q = 0.f;
    #pragma unroll
    for (int j = 0; j < 8; j++) { float d = v[j] - mean; q += d * d; }
    float var = block_reduce_sum256(q) * (1.f / DMODEL);
    float rstd = rsqrtf(var + 1e-5f);
    #pragma unroll
    for (int j = 0; j < 8; j++) {
        int i = threadIdx.x + 256 * j;
        float val = (v[j] - mean) * rstd * w[i] + b[i];
        size_t idx = (size_t)row * DMODEL + i;
        if (outf) outf[idx] = val;
        if (outh) {
            __nv_bfloat16 h, l; split_hi_lo(val, h, l);
            outh[idx] = h; outl[idx] = l;
        }
    }
}

// ------------------------- sheaf (writes fp32 u + bf16 hi/lo) --------------
__global__ void sheaf_kernel(const float* __restrict__ y,
                             const float* __restrict__ ctab,
                             const float* __restrict__ stab,
                             const float* __restrict__ alpha_p,
                             float* __restrict__ u,
                             __nv_bfloat16* __restrict__ uh,
                             __nv_bfloat16* __restrict__ ul) {
    int row = blockIdx.x;
    int t = row & (TLEN - 1);
    float a = fabsf(alpha_p[0]);
    const float* yr = y + (size_t)row * DMODEL;
    #pragma unroll
    for (int jj = 0; jj < 4; jj++) {
        int p = threadIdx.x + 256 * jj;
        float r0 = yr[p], i0 = yr[p + DHALF];
        float lr = 4.f * r0, li = 4.f * i0;
        #pragma unroll
        for (int idx = 0; idx < 4; idx++) {
            int delta = idx - 3;
            float rs, is;
            if (delta == 0) { rs = r0; is = i0; }
            else if (t + delta >= 0) {
                const float* ys = y + (size_t)(row + delta) * DMODEL;
                rs = ys[p]; is = ys[p + DHALF];
            } else { rs = 0.f; is = 0.f; }
            float c = ctab[idx * DHALF + p], s = stab[idx * DHALF + p];
            lr -= c * rs + s * is;
            li -= c * is - s * rs;
        }
        float outr = r0 - a * lr, outi = i0 - a * li;
        size_t br = (size_t)row * DMODEL + p, bi = br + DHALF;
        u[br] = outr; u[bi] = outi;
        __nv_bfloat16 h, l;
        split_hi_lo(outr, h, l); uh[br] = h; ul[br] = l;
        split_hi_lo(outi, h, l); uh[bi] = h; ul[bi] = l;
    }
}

// ------------------------- fused gist rotation block ------------------------
__global__ void gist_rot_kernel(const float* __restrict__ x1,
                                const float* __restrict__ lw, const float* __restrict__ lb,
                                const float* __restrict__ grw, const float* __restrict__ grb,
                                const float* __restrict__ gc, const float* __restrict__ gs,
                                float* __restrict__ x2) {
    int row = blockIdx.x;
    int b = row >> 11;
    const float* p = x1 + (size_t)row * DMODEL;
    float xr[4], xi[4];
    #pragma unroll
    for (int jj = 0; jj < 4; jj++) {
        int q = threadIdx.x + 256 * jj;
        xr[jj] = p[q]; xi[jj] = p[q + DHALF];
    }
    float s1 = 0.f;
    #pragma unroll
    for (int jj = 0; jj < 4; jj++) s1 += xr[jj] + xi[jj];
    float m1 = block_reduce_sum256(s1) * (1.f / DMODEL);
    float q1 = 0.f;
    #pragma unroll
    for (int jj = 0; jj < 4; jj++) {
        float dr = xr[jj] - m1, di = xi[jj] - m1;
        q1 += dr * dr + di * di;
    }
    float rstd1 = rsqrtf(block_reduce_sum256(q1) * (1.f / DMODEL) + 1e-5f);

    float xnr[4], xni[4], rr[4], ri[4];
    #pragma unroll
    for (int jj = 0; jj < 4; jj++) {
        int q = threadIdx.x + 256 * jj;
        xnr[jj] = (xr[jj] - m1) * rstd1 * lw[q] + lb[q];
        xni[jj] = (xi[jj] - m1) * rstd1 * lw[q + DHALF] + lb[q + DHALF];
        float c = gc[b * DHALF + q], sn = gs[b * DHALF + q];
        rr[jj] = xnr[jj] * c - xni[jj] * sn;
        ri[jj] = xnr[jj] * sn + xni[jj] * c;
    }
    float s2 = 0.f;
    #pragma unroll
    for (int jj = 0; jj < 4; jj++) s2 += rr[jj] + ri[jj];
    float m2 = block_reduce_sum256(s2) * (1.f / DMODEL);
    float q2 = 0.f;
    #pragma unroll
    for (int jj = 0; jj < 4; jj++) {
        float dr = rr[jj] - m2, di = ri[jj] - m2;
        q2 += dr * dr + di * di;
    }
    float rstd2 = rsqrtf(block_reduce_sum256(q2) * (1.f / DMODEL) + 1e-5f);

    #pragma unroll
    for (int jj = 0; jj < 4; jj++) {
        int q = threadIdx.x + 256 * jj;
        float outr = xr[jj] + (rr[jj] - m2) * rstd2 * grw[q] + grb[q] - xnr[jj];
        float outi = xi[jj] + (ri[jj] - m2) * rstd2 * grw[q + DHALF] + grb[q + DHALF] - xni[jj];
        x2[(size_t)row * DMODEL + q]         = outr;
        x2[(size_t)row * DMODEL + q + DHALF] = outi;
    }
}

// ------------------------- fp32 GEMM (small M=64 cases only) ----------------
__global__ __launch_bounds__(256, 2)
void gemm_kernel(const float* __restrict__ A, int lda,
                 const float* __restrict__ W, int ldb,
                 float* __restrict__ D, int ldd,
                 const float* __restrict__ add1,
                 const float* __restrict__ add2,
                 const float* __restrict__ bias,
                 int M, int Kdim) {
    __shared__ float As[16][132];
    __shared__ float Bs[16][132];
    const int m0 = blockIdx.y * 128, n0 = blockIdx.x * 128;
    const int tid = threadIdx.x, tx = tid & 15, ty = tid >> 4;
    float acc[8][8];
    #pragma unroll
    for (int i = 0; i < 8; i++)
        #pragma unroll
        for (int j = 0; j < 8; j++) acc[i][j] = 0.f;

    for (int k0 = 0; k0 < Kdim; k0 += 16) {
        #pragma unroll
        for (int i = 0; i < 2; i++) {
            int f  = tid + 256 * i;
            int rm = f >> 2;
            int kc = (f & 3) << 2;
            float4 av = make_float4(0.f, 0.f, 0.f, 0.f);
            if (m0 + rm < M) av = *(const float4*)(A + (size_t)(m0 + rm) * lda + k0 + kc);
            As[kc + 0][rm] = av.x; As[kc + 1][rm] = av.y;
            As[kc + 2][rm] = av.z; As[kc + 3][rm] = av.w;
            float4 bv = *(const float4*)(W + (size_t)(n0 + rm) * ldb + k0 + kc);
            Bs[kc + 0][rm] = bv.x; Bs[kc + 1][rm] = bv.y;
            Bs[kc + 2][rm] = bv.z; Bs[kc + 3][rm] = bv.w;
        }
        __syncthreads();
        #pragma unroll
        for (int k = 0; k < 16; k++) {
            float ra[8], rb[8];
            #pragma unroll
            for (int i = 0; i < 8; i++) ra[i] = As[k][ty * 8 + i];
            #pragma unroll
            for (int j = 0; j < 8; j++) rb[j] = Bs[k][tx * 8 + j];
            #pragma unroll
            for (int i = 0; i < 8; i++)
                #pragma unroll
                for (int j = 0; j < 8; j++) acc[i][j] += ra[i] * rb[j];
        }
        __syncthreads();
    }

    #pragma unroll
    for (int i = 0; i < 8; i++) {
        int m = m0 + ty * 8 + i;
        if (m < M) {
            #pragma unroll
            for (int j = 0; j < 8; j++) {
                int n = n0 + tx * 8 + j;
                float v = acc[i][j];
                if (bias) v += bias[n];
                size_t idx = (size_t)m * ldd + n;
                if (add1) v += add1[idx];
                if (add2) v += add2[idx];
                D[idx] = v;
            }
        }
    }
}

// ------------------------- bf16 HMMA 3-term GEMM ----------------------------
// D[m,n] = sum_k (Ahi+Alo)[m,k]*(Whi+Wlo)[n,k]  (3 terms: hh + hl + lh)
// CTA tile 128x128, BK=64, 8 warps (4 m x 2 n), warp tile 32x64.
#define GBK 64
#define ROWP 72                         // padded row: 72 bf16 = 144 B (36 words)
#define TILE_E (128 * ROWP)
#define STAGE_E (4 * TILE_E)
#define SMEM_GEMM (2 * STAGE_E * 2)     // bytes = 147456

__device__ __forceinline__ uint32_t lds32(const __nv_bfloat16* base, int eoff) {
    return *reinterpret_cast<const uint32_t*>(base + eoff);
}

__global__ __launch_bounds__(256, 1)
void gemm_bf16_kernel(const __nv_bfloat16* __restrict__ Ahi,
                      const __nv_bfloat16* __restrict__ Alo,
                      const __nv_bfloat16* __restrict__ Whi,
                      const __nv_bfloat16* __restrict__ Wlo,
                      float* __restrict__ D,
                      const float* __restrict__ add1,
                      const float* __restrict__ add2) {
    extern __shared__ __nv_bfloat16 sm[];
    const int tid  = threadIdx.x;
    const int lane = tid & 31;
    const int warp = tid >> 5;
    const int wm = warp & 3;
    const int wn = warp >> 2;
    const int m0 = blockIdx.y * 128, n0 = blockIdx.x * 128;
    const uint32_t smb = smem_u32(sm);

    float acc[2][8][4];
    #pragma unroll
    for (int mt = 0; mt < 2; mt++)
        #pragma unroll
        for (int nt = 0; nt < 8; nt++)
            #pragma unroll
            for (int j = 0; j < 4; j++) acc[mt][nt][j] = 0.f;

    const int NCHUNK = DMODEL / GBK;    // 32

    // prologue: load stage 0
    {
        const __nv_bfloat16* srcs[4] = { Ahi + (size_t)m0 * DMODEL,
                                         Alo + (size_t)m0 * DMODEL,
                                         Whi + (size_t)n0 * DMODEL,
                                         Wlo + (size_t)n0 * DMODEL };
        #pragma unroll
        for (int t = 0; t < 4; t++) {
            uint32_t tb = smb + t * TILE_E * 2;
            #pragma unroll
            for (int i = 0; i < 4; i++) {
                int idx = tid + i * 256;
                int row = idx >> 3, ch = idx & 7;
                cpasync16(tb + row * (ROWP * 2) + ch * 16,
                          srcs[t] + (size_t)row * DMODEL + ch * 8);
            }
        }
        CP_COMMIT();
    }

    for (int kc = 0; kc < NCHUNK; kc++) {
        if (kc + 1 < NCHUNK) {
            const int buf = (kc + 1) & 1;
            const int k0 = (kc + 1) * GBK;
            const __nv_bfloat16* srcs[4] = { Ahi + (size_t)m0 * DMODEL + k0,
                                             Alo + (size_t)m0 * DMODEL + k0,
                                             Whi + (size_t)n0 * DMODEL + k0,
                                             Wlo + (size_t)n0 * DMODEL + k0 };
            uint32_t sbase = smb + buf * STAGE_E * 2;
            #pragma unroll
            for (int t = 0; t < 4; t++) {
                uint32_t tb = sbase + t * TILE_E * 2;
                #pragma unroll
                for (int i = 0; i < 4; i++) {
                    int idx = tid + i * 256;
                    int row = idx >> 3, ch = idx & 7;
                    cpasync16(tb + row * (ROWP * 2) + ch * 16,
                              srcs[t] + (size_t)row * DMODEL + ch * 8);
                }
            }
            CP_COMMIT();
            CP_WAIT(1);
        } else {
            CP_WAIT(0);
        }
        __syncthreads();

        const __nv_bfloat16* sbuf = sm + (kc & 1) * STAGE_E;
        const __nv_bfloat16* ahiT = sbuf;
        const __nv_bfloat16* aloT = sbuf + TILE_E;
        const __nv_bfloat16* whiT = sbuf + 2 * TILE_E;
        const __nv_bfloat16* wloT = sbuf + 3 * TILE_E;
        const int r  = lane >> 2;
        const int c2 = lane & 3;

        #pragma unroll
        for (int ks = 0; ks < 4; ks++) {
            const int kb = ks * 16 + c2 * 2;
            uint32_t ah[2][4], al[2][4];
            #pragma unroll
            for (int mt = 0; mt < 2; mt++) {
                int rowb = wm * 32 + mt * 16 + r;
                ah[mt][0] = lds32(ahiT, rowb * ROWP + kb);
                ah[mt][1] = lds32(ahiT, (rowb + 8) * ROWP + kb);
                ah[mt][2] = lds32(ahiT, rowb * ROWP + kb + 8);
                ah[mt][3] = lds32(ahiT, (rowb + 8) * ROWP + kb + 8);
                al[mt][0] = lds32(aloT, rowb * ROWP + kb);
                al[mt][1] = lds32(aloT, (rowb + 8) * ROWP + kb);
                al[mt][2] = lds32(aloT, rowb * ROWP + kb + 8);
                al[mt][3] = lds32(aloT, (rowb + 8) * ROWP + kb + 8);
            }
            #pragma unroll
            for (int nt = 0; nt < 8; nt++) {
                int nb = wn * 64 + nt * 8 + r;
                uint32_t bh0 = lds32(whiT, nb * ROWP + kb);
                uint32_t bh1 = lds32(whiT, nb * ROWP + kb + 8);
                uint32_t bl0 = lds32(wloT, nb * ROWP + kb);
                uint32_t bl1 = lds32(wloT, nb * ROWP + kb + 8);
                #pragma unroll
                for (int mt = 0; mt < 2; mt++) {
                    mma16816(acc[mt][nt], ah[mt], bh0, bh1);
                    mma16816(acc[mt][nt], ah[mt], bl0, bl1);
                    mma16816(acc[mt][nt], al[mt], bh0, bh1);
                }
            }
        }
        __syncthreads();
    }

    // epilogue
    const int r  = lane >> 2;
    const int c2 = lane & 3;
    #pragma unroll
    for (int mt = 0; mt < 2; mt++) {
        #pragma unroll
        for (int nt = 0; nt < 8; nt++) {
            int row0 = m0 + wm * 32 + mt * 16 + r;
            int col  = n0 + wn * 64 + nt * 8 + c2 * 2;
            size_t i0 = (size_t)row0 * DMODEL + col;
            size_t i1 = i0 + (size_t)8 * DMODEL;
            float2 v0 = make_float2(acc[mt][nt][0], acc[mt][nt][1]);
            float2 v1 = make_float2(acc[mt][nt][2], acc[mt][nt][3]);
            if (add1) {
                float2 a0 = *(const float2*)(add1 + i0);
                float2 a1 = *(const float2*)(add1 + i1);
                v0.x += a0.x; v0.y += a0.y; v1.x += a1.x; v1.y += a1.y;
            }
            if (add2) {
                float2 a0 = *(const float2*)(add2 + i0);
                float2 a1 = *(const float2*)(add2 + i1);
                v0.x += a0.x; v0.y += a0.y; v1.x += a1.x; v1.y += a1.y;
            }
            *(float2*)(D + i0) = v0;
            *(float2*)(D + i1) = v1;
        }
    }
}

// ------------------------- gist cross-attention (16 kv tokens) ---------------
__global__ void attn_kernel(const float* __restrict__ Q,
                            const float* __restrict__ Kh,
                            const float* __restrict__ V,
                            __nv_bfloat16* __restrict__ ch,
                            __nv_bfloat16* __restrict__ cl) {
    __shared__ float Ks[KGIST][HDIM];
    __shared__ float Vs[KGIST][HDIM];
    const int h = blockIdx.y, b = blockIdx.z;
    const int t0 = blockIdx.x * 32;
    for (int j = threadIdx.x; j < KGIST * HDIM; j += 256) {
        int k = j >> 7, c = j & 127;
        Ks[k][c] = Kh[(size_t)(b * KGIST + k) * DMODEL + h * HDIM + c];
        Vs[k][c] = V [(size_t)(b * KGIST + k) * DMODEL + h * HDIM + c];
    }
    __syncthreads();
    const int w = threadIdx.x >> 5, lane = threadIdx.x & 31;
    const float scale = 0.08838834764831845f;
    for (int it = 0; it < 4; it++) {
        int t = t0 + w * 4 + it;
        size_t base = ((size_t)(b * TLEN + t)) * DMODEL + h * HDIM + lane * 4;
        float q0 = Q[base], q1 = Q[base + 1], q2 = Q[base + 2], q3 = Q[base + 3];
        float sc[KGIST];
        #pragma unroll
        for (int k = 0; k < KGIST; k++) {
            float ps = q0 * Ks[k][lane * 4] + q1 * Ks[k][lane * 4 + 1]
                     + q2 * Ks[k][lane * 4 + 2] + q3 * Ks[k][lane * 4 + 3];
            #pragma unroll
            for (int o = 16; o > 0; o >>= 1) ps += __shfl_xor_sync(0xffffffffu, ps, o);
            sc[k] = ps * scale;
        }
        float mx = sc[0];
        #pragma unroll
        for (int k = 1; k < KGIST; k++) mx = fmaxf(mx, sc[k]);
        float ssum = 0.f;
        #pragma unroll
        for (int k = 0; k < KGIST; k++) { sc[k] = expf(sc[k] - mx); ssum += sc[k]; }
        float inv = 1.f / ssum;
        float c0 = 0.f, c1 = 0.f, c2 = 0.f, c3 = 0.f;
        #pragma unroll
        for (int k = 0; k < KGIST; k++) {
            float wk = sc[k] * inv;
            c0 += wk * Vs[k][lane * 4];
            c1 += wk * Vs[k][lane * 4 + 1];
            c2 += wk * Vs[k][lane * 4 + 2];
            c3 += wk * Vs[k][lane * 4 + 3];
        }
        __nv_bfloat16 hh, ll;
        split_hi_lo(c0, hh, ll); ch[base]     = hh; cl[base]     = ll;
        split_hi_lo(c1, hh, ll); ch[base + 1] = hh; cl[base + 1] = ll;
        split_hi_lo(c2, hh, ll); ch[base + 2] = hh; cl[base + 2] = ll;
        split_hi_lo(c3, hh, ll); ch[base + 3] = hh; cl[base + 3] = ll;
    }
}

// ------------------------- launcher -----------------------------------------
extern "C" void kernel_launch(void* const* d_in, const int* in_sizes, int n_in,
                              void* d_out, int out_size) {
    const float* x             = (const float*)d_in[0];
    const float* gist_theta    = (const float*)d_in[1];
    const float* gist_mag      = (const float*)d_in[2];
    const float* gist_weights  = (const float*)d_in[3];
    const float* ln_sheaf_w    = (const float*)d_in[4];
    const float* ln_sheaf_b    = (const float*)d_in[5];
    const float* sheaf_thetas  = (const float*)d_in[6];
    const float* alpha         = (const float*)d_in[7];
    const float* corr_W        = (const float*)d_in[8];
    const float* ln_gist_w     = (const float*)d_in[9];
    const float* ln_gist_b     = (const float*)d_in[10];
    const float* gist_strength = (const float*)d_in[11];
    const float* gr_ln_w       = (const float*)d_in[12];
    const float* gr_ln_b       = (const float*)d_in[13];
    const float* ln_gca_w      = (const float*)d_in[14];
    const float* ln_gca_b      = (const float*)d_in[15];
    const float* Wq            = (const float*)d_in[16];
    const float* Wk            = (const float*)d_in[17];
    const float* Wv            = (const float*)d_in[18];
    const float* Wo            = (const float*)d_in[19];
    const float* gist_up_W     = (const float*)d_in[20];
    const float* gist_up_b     = (const float*)d_in[21];
    float* out = (float*)d_out;

    float *y, *u, *x1, *x2, *q, *feat, *upw, *repr, *kh, *v, *shc, *shs, *gc, *gs;
    __nv_bfloat16 *ahi, *alo, *whi, *wlo;
    cudaGetSymbolAddress((void**)&y,    g_y);
    cudaGetSymbolAddress((void**)&u,    g_u);
    cudaGetSymbolAddress((void**)&x1,   g_x1);
    cudaGetSymbolAddress((void**)&x2,   g_x2);
    cudaGetSymbolAddress((void**)&q,    g_q);
    cudaGetSymbolAddress((void**)&feat, g_feat);
    cudaGetSymbolAddress((void**)&upw,  g_upw);
    cudaGetSymbolAddress((void**)&repr, g_repr);
    cudaGetSymbolAddress((void**)&kh,   g_kh);
    cudaGetSymbolAddress((void**)&v,    g_v);
    cudaGetSymbolAddress((void**)&shc,  g_shc);
    cudaGetSymbolAddress((void**)&shs,  g_shs);
    cudaGetSymbolAddress((void**)&gc,   g_gc);
    cudaGetSymbolAddress((void**)&gs,   g_gs);
    cudaGetSymbolAddress((void**)&ahi,  g_ahi);
    cudaGetSymbolAddress((void**)&alo,  g_alo);
    cudaGetSymbolAddress((void**)&whi,  g_whi);
    cudaGetSymbolAddress((void**)&wlo,  g_wlo);

    cudaFuncSetAttribute(gemm_bf16_kernel,
                         cudaFuncAttributeMaxDynamicSharedMemorySize, SMEM_GEMM);

    dim3 ggemm(DMODEL / 128, NROWS / 128);   // (16, 64)
    dim3 gsm(16, 1);
    const int wsplit4 = DMODEL * DMODEL / 4;

    // prep
    prep_sheaf_cs_kernel<<<16, 256>>>(sheaf_thetas, shc, shs);
    gist_theta_kernel<<<BATCH, 256>>>(gist_theta, gist_mag, gist_weights, gist_strength, gc, gs);
    feat_kernel<<<BATCH * KGIST, 256>>>(gist_theta, gist_mag, feat);
    pad_upw_kernel<<<DMODEL, 256>>>(gist_up_W, upw);

    // gist K/V path (small, fp32 FFMA)
    gemm_kernel<<<gsm, 256>>>(feat, KPAD, upw, KPAD, repr, DMODEL, nullptr, nullptr, gist_up_b, BATCH * KGIST, KPAD);
    gemm_kernel<<<gsm, 256>>>(repr, DMODEL, Wk, DMODEL, kh, DMODEL, nullptr, nullptr, nullptr, BATCH * KGIST, DMODEL);
    gemm_kernel<<<gsm, 256>>>(repr, DMODEL, Wv, DMODEL, v,  DMODEL, nullptr, nullptr, nullptr, BATCH * KGIST, DMODEL);

    // stage 1: sheaf residual
    ln_kernel<<<NROWS, 256>>>(x, ln_sheaf_w, ln_sheaf_b, y, nullptr, nullptr);
    sheaf_kernel<<<NROWS, 256>>>(y, shc, shs, alpha, u, ahi, alo);
    split_kernel<<<(wsplit4 + 255) / 256, 256>>>(corr_W, whi, wlo, wsplit4);
    gemm_bf16_kernel<<<ggemm, 256, SMEM_GEMM>>>(ahi, alo, whi, wlo, x1, x, u);

    // stage 2: gist rotation residual (fused)
    gist_rot_kernel<<<NROWS, 256>>>(x1, ln_gist_w, ln_gist_b, gr_ln_w, gr_ln_b, gc, gs, x2);

    // stage 3: gist cross-attention residual
    ln_kernel<<<NROWS, 256>>>(x2, ln_gca_w, ln_gca_b, nullptr, ahi, alo);
    split_kernel<<<(wsplit4 + 255) / 256, 256>>>(Wq, whi, wlo, wsplit4);
    gemm_bf16_kernel<<<ggemm, 256, SMEM_GEMM>>>(ahi, alo, whi, wlo, q, nullptr, nullptr);
    attn_kernel<<<dim3(TLEN / 32, NHEADS, BATCH), 256>>>(q, kh, v, ahi, alo);
    split_kernel<<<(wsplit4 + 255) / 256, 256>>>(Wo, whi, wlo, wsplit4);
    gemm_bf16_kernel<<<ggemm, 256, SMEM_GEMM>>>(ahi, alo, whi, wlo, out, x2, nullptr);

    (void)in_sizes; (void)n_in; (void)out_size;
}

// round 7
// speedup vs baseline: 2.7087x; 1.2928x over previous
#include <cuda_runtime.h>
#include <cuda_bf16.h>
#include <cuda.h>
#include <math.h>
#include <cstdint>

// Problem constants
#define BATCH 4
#define TLEN 2048
#define DMODEL 2048
#define DHALF 1024
#define NROWS (BATCH * TLEN)          // 8192
#define KGIST 16
#define NHEADS 16
#define HDIM 128
#define KUP 1025                       // gist_up feature dim (dh + 1)
#define MAXPART 32

// ------------------------- scratch (device globals; no allocation) ---------
__device__ float g_y [NROWS * DMODEL];
__device__ float g_u [NROWS * DMODEL];
__device__ float g_x1[NROWS * DMODEL];
__device__ float g_x2[NROWS * DMODEL];
__device__ float g_q [NROWS * DMODEL];
__device__ __nv_bfloat16 g_ahi[NROWS * DMODEL];
__device__ __nv_bfloat16 g_alo[NROWS * DMODEL];
__device__ __nv_bfloat16 g_whi[DMODEL * DMODEL];
__device__ __nv_bfloat16 g_wlo[DMODEL * DMODEL];
__device__ float g_feat[BATCH * KGIST * KUP];
__device__ float g_part[MAXPART * BATCH * KGIST * DMODEL];   // split-K partials (16 MB)
__device__ float g_repr[BATCH * KGIST * DMODEL];
__device__ float g_kh  [BATCH * KGIST * DMODEL];
__device__ float g_v   [BATCH * KGIST * DMODEL];
__device__ float g_shc[4 * DHALF];
__device__ float g_shs[4 * DHALF];
__device__ float g_gc [BATCH * DHALF];
__device__ float g_gs [BATCH * DHALF];

// ------------------------- helpers -----------------------------------------
__device__ __forceinline__ uint32_t smem_u32(const void* p) {
    uint32_t a;
    asm("{ .reg .u64 t; cvta.to.shared.u64 t, %1; cvt.u32.u64 %0, t; }" : "=r"(a) : "l"(p));
    return a;
}

__device__ __forceinline__ void cpasync16(uint32_t dst, const void* src) {
    asm volatile("cp.async.cg.shared.global [%0], [%1], 16;" :: "r"(dst), "l"(src));
}
#define CP_COMMIT() asm volatile("cp.async.commit_group;" ::: "memory")
#define CP_WAIT(n)  asm volatile("cp.async.wait_group %0;" :: "n"(n) : "memory")

__device__ __forceinline__ float block_reduce_sum256(float v) {
    __shared__ float sb[8];
    int lane = threadIdx.x & 31, wid = threadIdx.x >> 5;
    #pragma unroll
    for (int o = 16; o > 0; o >>= 1) v += __shfl_xor_sync(0xffffffffu, v, o);
    if (lane == 0) sb[wid] = v;
    __syncthreads();
    float r = 0.f;
    #pragma unroll
    for (int i = 0; i < 8; i++) r += sb[i];
    __syncthreads();
    return r;
}

__device__ __forceinline__ void split_hi_lo(float v, __nv_bfloat16& h, __nv_bfloat16& l) {
    h = __float2bfloat16(v);
    l = __float2bfloat16(v - __bfloat162float(h));
}

__device__ __forceinline__ void mma16816(float* d, const uint32_t* a, uint32_t b0, uint32_t b1) {
    asm volatile(
        "mma.sync.aligned.m16n8k16.row.col.f32.bf16.bf16.f32 "
        "{%0,%1,%2,%3}, {%4,%5,%6,%7}, {%8,%9}, {%0,%1,%2,%3};"
        : "+f"(d[0]), "+f"(d[1]), "+f"(d[2]), "+f"(d[3])
        : "r"(a[0]), "r"(a[1]), "r"(a[2]), "r"(a[3]), "r"(b0), "r"(b1));
}

// ------------------------- small prep kernels -------------------------------
__global__ void prep_sheaf_cs_kernel(const float* __restrict__ thetas,
                                     float* __restrict__ c, float* __restrict__ s) {
    int i = blockIdx.x * 256 + threadIdx.x;
    if (i < 4 * DHALF) { float th = thetas[i]; c[i] = cosf(th); s[i] = sinf(th); }
}

__global__ void gist_theta_kernel(const float* __restrict__ gtheta,
                                  const float* __restrict__ gmag,
                                  const float* __restrict__ gw,
                                  const float* __restrict__ gstrength,
                                  float* __restrict__ gc, float* __restrict__ gs) {
    int b = blockIdx.x;
    float wk[KGIST]; float wsum = 0.f;
    #pragma unroll
    for (int k = 0; k < KGIST; k++) { wk[k] = gw[b * KGIST + k] * gmag[b * KGIST + k]; wsum += wk[k]; }
    float inv = 1.f / (wsum + 1e-8f);
    float sig = 1.f / (1.f + expf(-gstrength[0]));
    for (int p = threadIdx.x; p < DHALF; p += 256) {
        float th = 0.f;
        #pragma unroll
        for (int k = 0; k < KGIST; k++) th += (wk[k] * inv) * gtheta[(size_t)(b * KGIST + k) * DHALF + p];
        th *= sig;
        gc[b * DHALF + p] = cosf(th);
        gs[b * DHALF + p] = sinf(th);
    }
}

__global__ void feat_kernel(const float* __restrict__ gtheta,
                            const float* __restrict__ gmag,
                            float* __restrict__ feat) {
    int r = blockIdx.x;           // 0..63
    for (int f = threadIdx.x; f < KUP; f += 256) {
        float v = (f < DHALF) ? gtheta[(size_t)r * DHALF + f] : gmag[r];
        feat[(size_t)r * KUP + f] = v;
    }
}

// fp32 -> bf16 hi/lo splitter (weights)
__global__ void split_kernel(const float* __restrict__ in,
                             __nv_bfloat16* __restrict__ hi,
                             __nv_bfloat16* __restrict__ lo, int n4) {
    int i = blockIdx.x * 256 + threadIdx.x;
    if (i >= n4) return;
    float4 v = ((const float4*)in)[i];
    __nv_bfloat16 h0, h1, h2, h3, l0, l1, l2, l3;
    split_hi_lo(v.x, h0, l0); split_hi_lo(v.y, h1, l1);
    split_hi_lo(v.z, h2, l2); split_hi_lo(v.w, h3, l3);
    ((__nv_bfloat162*)hi)[2 * i]     = __nv_bfloat162(h0, h1);
    ((__nv_bfloat162*)hi)[2 * i + 1] = __nv_bfloat162(h2, h3);
    ((__nv_bfloat162*)lo)[2 * i]     = __nv_bfloat162(l0, l1);
    ((__nv_bfloat162*)lo)[2 * i + 1] = __nv_bfloat162(l2, l3);
}

// ------------------------- LayerNorm (optionally emits bf16 hi/lo) ---------
__global__ void ln_kernel(const float* __restrict__ in,
                          const float* __restrict__ w,
                          const float* __restrict__ b,
                          float* __restrict__ outf,
                          __nv_bfloat16* __restrict__ outh,
                          __nv_bfloat16* __restrict__ outl) {
    int row = blockIdx.x;
    const float* p = in + (size_t)row * DMODEL;
    float v[8];
    #pragma unroll
    for (int j = 0; j < 8; j++) v[j] = p[threadIdx.x + 256 * j];
    float s = 0.f;
    #pragma unroll
    for (int j = 0; j < 8; j++) s += v[j];
    float mean = block_reduce_sum256(s) * (1.f / DMODEL);
    float q = 0.f;
    #pragma unroll
    for (int j = 0; j < 8; j++) { float d = v[j] - mean; q += d * d; }
    float var = block_reduce_sum256(q) * (1.f / DMODEL);
    float rstd = rsqrtf(var + 1e-5f);
    #pragma unroll
    for (int j = 0; j < 8; j++) {
        int i = threadIdx.x + 256 * j;
        float val = (v[j] - mean) * rstd * w[i] + b[i];
        size_t idx = (size_t)row * DMODEL + i;
        if (outf) outf[idx] = val;
        if (outh) {
            __nv_bfloat16 h, l; split_hi_lo(val, h, l);
            outh[idx] = h; outl[idx] = l;
        }
    }
}

// ------------------------- sheaf (writes fp32 u + bf16 hi/lo) --------------
__global__ void sheaf_kernel(const float* __restrict__ y,
                             const float* __restrict__ ctab,
                             const float* __restrict__ stab,
                             const float* __restrict__ alpha_p,
                             float* __restrict__ u,
                             __nv_bfloat16* __restrict__ uh,
                             __nv_bfloat16* __restrict__ ul) {
    int row = blockIdx.x;
    int t = row & (TLEN - 1);
    float a = fabsf(alpha_p[0]);
    const float* yr = y + (size_t)row * DMODEL;
    #pragma unroll
    for (int jj = 0; jj < 4; jj++) {
        int p = threadIdx.x + 256 * jj;
        float r0 = yr[p], i0 = yr[p + DHALF];
        float lr = 4.f * r0, li = 4.f * i0;
        #pragma unroll
        for (int idx = 0; idx < 4; idx++) {
            int delta = idx - 3;
            float rs, is;
            if (delta == 0) { rs = r0; is = i0; }
            else if (t + delta >= 0) {
                const float* ys = y + (size_t)(row + delta) * DMODEL;
                rs = ys[p]; is = ys[p + DHALF];
            } else { rs = 0.f; is = 0.f; }
            float c = ctab[idx * DHALF + p], s = stab[idx * DHALF + p];
            lr -= c * rs + s * is;
            li -= c * is - s * rs;
        }
        float outr = r0 - a * lr, outi = i0 - a * li;
        size_t br = (size_t)row * DMODEL + p, bi = br + DHALF;
        u[br] = outr; u[bi] = outi;
        __nv_bfloat16 h, l;
        split_hi_lo(outr, h, l); uh[br] = h; ul[br] = l;
        split_hi_lo(outi, h, l); uh[bi] = h; ul[bi] = l;
    }
}

// ------------------------- fused gist rotation block ------------------------
__global__ void gist_rot_kernel(const float* __restrict__ x1,
                                const float* __restrict__ lw, const float* __restrict__ lb,
                                const float* __restrict__ grw, const float* __restrict__ grb,
                                const float* __restrict__ gc, const float* __restrict__ gs,
                                float* __restrict__ x2) {
    int row = blockIdx.x;
    int b = row >> 11;
    const float* p = x1 + (size_t)row * DMODEL;
    float xr[4], xi[4];
    #pragma unroll
    for (int jj = 0; jj < 4; jj++) {
        int q = threadIdx.x + 256 * jj;
        xr[jj] = p[q]; xi[jj] = p[q + DHALF];
    }
    float s1 = 0.f;
    #pragma unroll
    for (int jj = 0; jj < 4; jj++) s1 += xr[jj] + xi[jj];
    float m1 = block_reduce_sum256(s1) * (1.f / DMODEL);
    float q1 = 0.f;
    #pragma unroll
    for (int jj = 0; jj < 4; jj++) {
        float dr = xr[jj] - m1, di = xi[jj] - m1;
        q1 += dr * dr + di * di;
    }
    float rstd1 = rsqrtf(block_reduce_sum256(q1) * (1.f / DMODEL) + 1e-5f);

    float xnr[4], xni[4], rr[4], ri[4];
    #pragma unroll
    for (int jj = 0; jj < 4; jj++) {
        int q = threadIdx.x + 256 * jj;
        xnr[jj] = (xr[jj] - m1) * rstd1 * lw[q] + lb[q];
        xni[jj] = (xi[jj] - m1) * rstd1 * lw[q + DHALF] + lb[q + DHALF];
        float c = gc[b * DHALF + q], sn = gs[b * DHALF + q];
        rr[jj] = xnr[jj] * c - xni[jj] * sn;
        ri[jj] = xnr[jj] * sn + xni[jj] * c;
    }
    float s2 = 0.f;
    #pragma unroll
    for (int jj = 0; jj < 4; jj++) s2 += rr[jj] + ri[jj];
    float m2 = block_reduce_sum256(s2) * (1.f / DMODEL);
    float q2 = 0.f;
    #pragma unroll
    for (int jj = 0; jj < 4; jj++) {
        float dr = rr[jj] - m2, di = ri[jj] - m2;
        q2 += dr * dr + di * di;
    }
    float rstd2 = rsqrtf(block_reduce_sum256(q2) * (1.f / DMODEL) + 1e-5f);

    #pragma unroll
    for (int jj = 0; jj < 4; jj++) {
        int q = threadIdx.x + 256 * jj;
        float outr = xr[jj] + (rr[jj] - m2) * rstd2 * grw[q] + grb[q] - xnr[jj];
        float outi = xi[jj] + (ri[jj] - m2) * rstd2 * grw[q + DHALF] + grb[q + DHALF] - xni[jj];
        x2[(size_t)row * DMODEL + q]         = outr;
        x2[(size_t)row * DMODEL + q + DHALF] = outi;
    }
}

// ------------------- split-K small GEMM (M=64, N=2048) ----------------------
// Partial: part[z][m][n] = sum_{k in slice z} A[m][k] * W[n][k]
// grid (N/64, nparts), block 256. Deterministic (no atomics).
#define SKC 64
__global__ __launch_bounds__(256, 4)
void smallgemm_kernel(const float* __restrict__ A, int lda,
                      const float* __restrict__ W, int ldw,
                      float* __restrict__ part, int Kdim) {
    __shared__ float Fs[64][SKC + 1];
    __shared__ float Ws[64][SKC + 1];
    const int n0 = blockIdx.x * 64;
    const int k0 = blockIdx.y * SKC;
    const int tid = threadIdx.x;

    for (int idx = tid; idx < 64 * SKC; idx += 256) {
        int r = idx >> 6, c = idx & 63;
        int k = k0 + c;
        Fs[r][c] = (k < Kdim) ? A[(size_t)r * lda + k] : 0.f;
        Ws[r][c] = (k < Kdim) ? W[(size_t)(n0 + r) * ldw + k] : 0.f;
    }
    __syncthreads();

    const int tx = tid & 15, ty = tid >> 4;   // 16x16 threads, 4x4 outputs each
    float acc[4][4];
    #pragma unroll
    for (int i = 0; i < 4; i++)
        #pragma unroll
        for (int j = 0; j < 4; j++) acc[i][j] = 0.f;

    for (int k = 0; k < SKC; k++) {
        float ra[4], rb[4];
        #pragma unroll
        for (int i = 0; i < 4; i++) ra[i] = Fs[ty * 4 + i][k];
        #pragma unroll
        for (int j = 0; j < 4; j++) rb[j] = Ws[tx * 4 + j][k];
        #pragma unroll
        for (int i = 0; i < 4; i++)
            #pragma unroll
            for (int j = 0; j < 4; j++) acc[i][j] += ra[i] * rb[j];
    }

    float* pz = part + (size_t)blockIdx.y * (64 * DMODEL);
    #pragma unroll
    for (int i = 0; i < 4; i++)
        #pragma unroll
        for (int j = 0; j < 4; j++)
            pz[(size_t)(ty * 4 + i) * DMODEL + n0 + tx * 4 + j] = acc[i][j];
}

// reduce partials: out[m][n] = sum_z part[z][m][n] + bias?[n]
__global__ void skreduce_kernel(const float* __restrict__ part, int nparts,
                                const float* __restrict__ bias,
                                float* __restrict__ out) {
    int idx = blockIdx.x * 256 + threadIdx.x;      // 0 .. 64*2048-1
    if (idx >= 64 * DMODEL) return;
    float s = bias ? bias[idx & (DMODEL - 1)] : 0.f;
    for (int z = 0; z < nparts; z++) s += part[(size_t)z * (64 * DMODEL) + idx];
    out[idx] = s;
}

// ------------------------- bf16 HMMA 3-term GEMM ----------------------------
#define GBK 64
#define ROWP 72
#define TILE_E (128 * ROWP)
#define STAGE_E (4 * TILE_E)
#define SMEM_GEMM (2 * STAGE_E * 2)     // bytes = 147456

__device__ __forceinline__ uint32_t lds32(const __nv_bfloat16* base, int eoff) {
    return *reinterpret_cast<const uint32_t*>(base + eoff);
}

__global__ __launch_bounds__(256, 1)
void gemm_bf16_kernel(const __nv_bfloat16* __restrict__ Ahi,
                      const __nv_bfloat16* __restrict__ Alo,
                      const __nv_bfloat16* __restrict__ Whi,
                      const __nv_bfloat16* __restrict__ Wlo,
                      float* __restrict__ D,
                      const float* __restrict__ add1,
                      const float* __restrict__ add2) {
    extern __shared__ __nv_bfloat16 sm[];
    const int tid  = threadIdx.x;
    const int lane = tid & 31;
    const int warp = tid >> 5;
    const int wm = warp & 3;
    const int wn = warp >> 2;
    const int m0 = blockIdx.y * 128, n0 = blockIdx.x * 128;
    const uint32_t smb = smem_u32(sm);

    float acc[2][8][4];
    #pragma unroll
    for (int mt = 0; mt < 2; mt++)
        #pragma unroll
        for (int nt = 0; nt < 8; nt++)
            #pragma unroll
            for (int j = 0; j < 4; j++) acc[mt][nt][j] = 0.f;

    const int NCHUNK = DMODEL / GBK;    // 32

    {
        const __nv_bfloat16* srcs[4] = { Ahi + (size_t)m0 * DMODEL,
                                         Alo + (size_t)m0 * DMODEL,
                                         Whi + (size_t)n0 * DMODEL,
                                         Wlo + (size_t)n0 * DMODEL };
        #pragma unroll
        for (int t = 0; t < 4; t++) {
            uint32_t tb = smb + t * TILE_E * 2;
            #pragma unroll
            for (int i = 0; i < 4; i++) {
                int idx = tid + i * 256;
                int row = idx >> 3, ch = idx & 7;
                cpasync16(tb + row * (ROWP * 2) + ch * 16,
                          srcs[t] + (size_t)row * DMODEL + ch * 8);
            }
        }
        CP_COMMIT();
    }

    for (int kc = 0; kc < NCHUNK; kc++) {
        if (kc + 1 < NCHUNK) {
            const int buf = (kc + 1) & 1;
            const int k0 = (kc + 1) * GBK;
            const __nv_bfloat16* srcs[4] = { Ahi + (size_t)m0 * DMODEL + k0,
                                             Alo + (size_t)m0 * DMODEL + k0,
                                             Whi + (size_t)n0 * DMODEL + k0,
                                             Wlo + (size_t)n0 * DMODEL + k0 };
            uint32_t sbase = smb + buf * STAGE_E * 2;
            #pragma unroll
            for (int t = 0; t < 4; t++) {
                uint32_t tb = sbase + t * TILE_E * 2;
                #pragma unroll
                for (int i = 0; i < 4; i++) {
                    int idx = tid + i * 256;
                    int row = idx >> 3, ch = idx & 7;
                    cpasync16(tb + row * (ROWP * 2) + ch * 16,
                              srcs[t] + (size_t)row * DMODEL + ch * 8);
                }
            }
            CP_COMMIT();
            CP_WAIT(1);
        } else {
            CP_WAIT(0);
        }
        __syncthreads();

        const __nv_bfloat16* sbuf = sm + (kc & 1) * STAGE_E;
        const __nv_bfloat16* ahiT = sbuf;
        const __nv_bfloat16* aloT = sbuf + TILE_E;
        const __nv_bfloat16* whiT = sbuf + 2 * TILE_E;
        const __nv_bfloat16* wloT = sbuf + 3 * TILE_E;
        const int r  = lane >> 2;
        const int c2 = lane & 3;

        #pragma unroll
        for (int ks = 0; ks < 4; ks++) {
            const int kb = ks * 16 + c2 * 2;
            uint32_t ah[2][4], al[2][4];
            #pragma unroll
            for (int mt = 0; mt < 2; mt++) {
                int rowb = wm * 32 + mt * 16 + r;
                ah[mt][0] = lds32(ahiT, rowb * ROWP + kb);
                ah[mt][1] = lds32(ahiT, (rowb + 8) * ROWP + kb);
                ah[mt][2] = lds32(ahiT, rowb * ROWP + kb + 8);
                ah[mt][3] = lds32(ahiT, (rowb + 8) * ROWP + kb + 8);
                al[mt][0] = lds32(aloT, rowb * ROWP + kb);
                al[mt][1] = lds32(aloT, (rowb + 8) * ROWP + kb);
                al[mt][2] = lds32(aloT, rowb * ROWP + kb + 8);
                al[mt][3] = lds32(aloT, (rowb + 8) * ROWP + kb + 8);
            }
            #pragma unroll
            for (int nt = 0; nt < 8; nt++) {
                int nb = wn * 64 + nt * 8 + r;
                uint32_t bh0 = lds32(whiT, nb * ROWP + kb);
                uint32_t bh1 = lds32(whiT, nb * ROWP + kb + 8);
                uint32_t bl0 = lds32(wloT, nb * ROWP + kb);
                uint32_t bl1 = lds32(wloT, nb * ROWP + kb + 8);
                #pragma unroll
                for (int mt = 0; mt < 2; mt++) {
                    mma16816(acc[mt][nt], ah[mt], bh0, bh1);
                    mma16816(acc[mt][nt], ah[mt], bl0, bl1);
                    mma16816(acc[mt][nt], al[mt], bh0, bh1);
                }
            }
        }
        __syncthreads();
    }

    const int r  = lane >> 2;
    const int c2 = lane & 3;
    #pragma unroll
    for (int mt = 0; mt < 2; mt++) {
        #pragma unroll
        for (int nt = 0; nt < 8; nt++) {
            int row0 = m0 + wm * 32 + mt * 16 + r;
            int col  = n0 + wn * 64 + nt * 8 + c2 * 2;
            size_t i0 = (size_t)row0 * DMODEL + col;
            size_t i1 = i0 + (size_t)8 * DMODEL;
            float2 v0 = make_float2(acc[mt][nt][0], acc[mt][nt][1]);
            float2 v1 = make_float2(acc[mt][nt][2], acc[mt][nt][3]);
            if (add1) {
                float2 a0 = *(const float2*)(add1 + i0);
                float2 a1 = *(const float2*)(add1 + i1);
                v0.x += a0.x; v0.y += a0.y; v1.x += a1.x; v1.y += a1.y;
            }
            if (add2) {
                float2 a0 = *(const float2*)(add2 + i0);
                float2 a1 = *(const float2*)(add2 + i1);
                v0.x += a0.x; v0.y += a0.y; v1.x += a1.x; v1.y += a1.y;
            }
            *(float2*)(D + i0) = v0;
            *(float2*)(D + i1) = v1;
        }
    }
}

// ------------------------- gist cross-attention (16 kv tokens) ---------------
__global__ void attn_kernel(const float* __restrict__ Q,
                            const float* __restrict__ Kh,
                            const float* __restrict__ V,
                            __nv_bfloat16* __restrict__ ch,
                            __nv_bfloat16* __restrict__ cl) {
    __shared__ float Ks[KGIST][HDIM];
    __shared__ float Vs[KGIST][HDIM];
    const int h = blockIdx.y, b = blockIdx.z;
    const int t0 = blockIdx.x * 32;
    for (int j = threadIdx.x; j < KGIST * HDIM; j += 256) {
        int k = j >> 7, c = j & 127;
        Ks[k][c] = Kh[(size_t)(b * KGIST + k) * DMODEL + h * HDIM + c];
        Vs[k][c] = V [(size_t)(b * KGIST + k) * DMODEL + h * HDIM + c];
    }
    __syncthreads();
    const int w = threadIdx.x >> 5, lane = threadIdx.x & 31;
    const float scale = 0.08838834764831845f;
    for (int it = 0; it < 4; it++) {
        int t = t0 + w * 4 + it;
        size_t base = ((size_t)(b * TLEN + t)) * DMODEL + h * HDIM + lane * 4;
        float q0 = Q[base], q1 = Q[base + 1], q2 = Q[base + 2], q3 = Q[base + 3];
        float sc[KGIST];
        #pragma unroll
        for (int k = 0; k < KGIST; k++) {
            float ps = q0 * Ks[k][lane * 4] + q1 * Ks[k][lane * 4 + 1]
                     + q2 * Ks[k][lane * 4 + 2] + q3 * Ks[k][lane * 4 + 3];
            #pragma unroll
            for (int o = 16; o > 0; o >>= 1) ps += __shfl_xor_sync(0xffffffffu, ps, o);
            sc[k] = ps * scale;
        }
        float mx = sc[0];
        #pragma unroll
        for (int k = 1; k < KGIST; k++) mx = fmaxf(mx, sc[k]);
        float ssum = 0.f;
        #pragma unroll
        for (int k = 0; k < KGIST; k++) { sc[k] = expf(sc[k] - mx); ssum += sc[k]; }
        float inv = 1.f / ssum;
        float c0 = 0.f, c1 = 0.f, c2 = 0.f, c3 = 0.f;
        #pragma unroll
        for (int k = 0; k < KGIST; k++) {
            float wk = sc[k] * inv;
            c0 += wk * Vs[k][lane * 4];
            c1 += wk * Vs[k][lane * 4 + 1];
            c2 += wk * Vs[k][lane * 4 + 2];
            c3 += wk * Vs[k][lane * 4 + 3];
        }
        __nv_bfloat16 hh, ll;
        split_hi_lo(c0, hh, ll); ch[base]     = hh; cl[base]     = ll;
        split_hi_lo(c1, hh, ll); ch[base + 1] = hh; cl[base + 1] = ll;
        split_hi_lo(c2, hh, ll); ch[base + 2] = hh; cl[base + 2] = ll;
        split_hi_lo(c3, hh, ll); ch[base + 3] = hh; cl[base + 3] = ll;
    }
}

// ------------------------- launcher -----------------------------------------
extern "C" void kernel_launch(void* const* d_in, const int* in_sizes, int n_in,
                              void* d_out, int out_size) {
    const float* x             = (const float*)d_in[0];
    const float* gist_theta    = (const float*)d_in[1];
    const float* gist_mag      = (const float*)d_in[2];
    const float* gist_weights  = (const float*)d_in[3];
    const float* ln_sheaf_w    = (const float*)d_in[4];
    const float* ln_sheaf_b    = (const float*)d_in[5];
    const float* sheaf_thetas  = (const float*)d_in[6];
    const float* alpha         = (const float*)d_in[7];
    const float* corr_W        = (const float*)d_in[8];
    const float* ln_gist_w     = (const float*)d_in[9];
    const float* ln_gist_b     = (const float*)d_in[10];
    const float* gist_strength = (const float*)d_in[11];
    const float* gr_ln_w       = (const float*)d_in[12];
    const float* gr_ln_b       = (const float*)d_in[13];
    const float* ln_gca_w      = (const float*)d_in[14];
    const float* ln_gca_b      = (const float*)d_in[15];
    const float* Wq            = (const float*)d_in[16];
    const float* Wk            = (const float*)d_in[17];
    const float* Wv            = (const float*)d_in[18];
    const float* Wo            = (const float*)d_in[19];
    const float* gist_up_W     = (const float*)d_in[20];
    const float* gist_up_b     = (const float*)d_in[21];
    float* out = (float*)d_out;

    float *y, *u, *x1, *x2, *q, *feat, *part, *repr, *kh, *v, *shc, *shs, *gc, *gs;
    __nv_bfloat16 *ahi, *alo, *whi, *wlo;
    cudaGetSymbolAddress((void**)&y,    g_y);
    cudaGetSymbolAddress((void**)&u,    g_u);
    cudaGetSymbolAddress((void**)&x1,   g_x1);
    cudaGetSymbolAddress((void**)&x2,   g_x2);
    cudaGetSymbolAddress((void**)&q,    g_q);
    cudaGetSymbolAddress((void**)&feat, g_feat);
    cudaGetSymbolAddress((void**)&part, g_part);
    cudaGetSymbolAddress((void**)&repr, g_repr);
    cudaGetSymbolAddress((void**)&kh,   g_kh);
    cudaGetSymbolAddress((void**)&v,    g_v);
    cudaGetSymbolAddress((void**)&shc,  g_shc);
    cudaGetSymbolAddress((void**)&shs,  g_shs);
    cudaGetSymbolAddress((void**)&gc,   g_gc);
    cudaGetSymbolAddress((void**)&gs,   g_gs);
    cudaGetSymbolAddress((void**)&ahi,  g_ahi);
    cudaGetSymbolAddress((void**)&alo,  g_alo);
    cudaGetSymbolAddress((void**)&whi,  g_whi);
    cudaGetSymbolAddress((void**)&wlo,  g_wlo);

    cudaFuncSetAttribute(gemm_bf16_kernel,
                         cudaFuncAttributeMaxDynamicSharedMemorySize, SMEM_GEMM);

    dim3 ggemm(DMODEL / 128, NROWS / 128);   // (16, 64)
    const int wsplit4 = DMODEL * DMODEL / 4;
    const int kp_up = (KUP + SKC - 1) / SKC;       // 17
    const int kp_d  = DMODEL / SKC;                // 32
    const int redgrid = (64 * DMODEL + 255) / 256; // 512

    // prep
    prep_sheaf_cs_kernel<<<16, 256>>>(sheaf_thetas, shc, shs);
    gist_theta_kernel<<<BATCH, 256>>>(gist_theta, gist_mag, gist_weights, gist_strength, gc, gs);
    feat_kernel<<<BATCH * KGIST, 256>>>(gist_theta, gist_mag, feat);

    // gist K/V path: split-K small GEMMs (deterministic two-phase)
    smallgemm_kernel<<<dim3(32, kp_up), 256>>>(feat, KUP, gist_up_W, KUP, part, KUP);
    skreduce_kernel<<<redgrid, 256>>>(part, kp_up, gist_up_b, repr);
    smallgemm_kernel<<<dim3(32, kp_d), 256>>>(repr, DMODEL, Wk, DMODEL, part, DMODEL);
    skreduce_kernel<<<redgrid, 256>>>(part, kp_d, nullptr, kh);
    smallgemm_kernel<<<dim3(32, kp_d), 256>>>(repr, DMODEL, Wv, DMODEL, part, DMODEL);
    skreduce_kernel<<<redgrid, 256>>>(part, kp_d, nullptr, v);

    // stage 1: sheaf residual
    ln_kernel<<<NROWS, 256>>>(x, ln_sheaf_w, ln_sheaf_b, y, nullptr, nullptr);
    sheaf_kernel<<<NROWS, 256>>>(y, shc, shs, alpha, u, ahi, alo);
    split_kernel<<<(wsplit4 + 255) / 256, 256>>>(corr_W, whi, wlo, wsplit4);
    gemm_bf16_kernel<<<ggemm, 256, SMEM_GEMM>>>(ahi, alo, whi, wlo, x1, x, u);

    // stage 2: gist rotation residual (fused)
    gist_rot_kernel<<<NROWS, 256>>>(x1, ln_gist_w, ln_gist_b, gr_ln_w, gr_ln_b, gc, gs, x2);

    // stage 3: gist cross-attention residual
    ln_kernel<<<NROWS, 256>>>(x2, ln_gca_w, ln_gca_b, nullptr, ahi, alo);
    split_kernel<<<(wsplit4 + 255) / 256, 256>>>(Wq, whi, wlo, wsplit4);
    gemm_bf16_kernel<<<ggemm, 256, SMEM_GEMM>>>(ahi, alo, whi, wlo, q, nullptr, nullptr);
    attn_kernel<<<dim3(TLEN / 32, NHEADS, BATCH), 256>>>(q, kh, v, ahi, alo);
    split_kernel<<<(wsplit4 + 255) / 256, 256>>>(Wo, whi, wlo, wsplit4);
    gemm_bf16_kernel<<<ggemm, 256, SMEM_GEMM>>>(ahi, alo, whi, wlo, out, x2, nullptr);

    (void)in_sizes; (void)n_in; (void)out_size;
}